// round 3
// baseline (speedup 1.0000x reference)
#include <cuda_runtime.h>
#include <math.h>

#define NN   100000
#define EE   1600000
#define HIDD 128

// ------------------------- scratch (__device__ globals) ---------------------
__device__ int   g_deg   [NN];
__device__ int   g_start [NN];
__device__ int   g_cursor[NN];
__device__ int   g_csr   [EE];      // src node per (dst-grouped) slot
__device__ float g_h0[(size_t)NN * HIDD];
__device__ float g_h1[(size_t)NN * HIDD];

// ------------------------- f32x2 packed helpers -----------------------------
__device__ __forceinline__ unsigned long long pack2(float lo, float hi) {
    unsigned long long r;
    asm("mov.b64 %0, {%1, %2};" : "=l"(r) : "f"(lo), "f"(hi));
    return r;
}
__device__ __forceinline__ unsigned long long fma2(unsigned long long a,
                                                   unsigned long long b,
                                                   unsigned long long c) {
    unsigned long long d;
    asm("fma.rn.f32x2 %0, %1, %2, %3;" : "=l"(d) : "l"(a), "l"(b), "l"(c));
    return d;
}
__device__ __forceinline__ float2 unpack2(unsigned long long v) {
    float2 f;
    asm("mov.b64 {%0, %1}, %2;" : "=f"(f.x), "=f"(f.y) : "l"(v));
    return f;
}

// ------------------------- CSR build ----------------------------------------
__global__ void zero_deg_kernel() {
    int i = blockIdx.x * blockDim.x + threadIdx.x;
    if (i < NN) g_deg[i] = 0;
}

__global__ void deg_kernel(const int* __restrict__ ei) {
    int e = blockIdx.x * blockDim.x + threadIdx.x;
    if (e < EE) atomicAdd(&g_deg[ei[EE + e]], 1);
}

// single-block exclusive scan over 100k degrees -> start & cursor
__global__ void scan_kernel() {
    __shared__ int part[1024];
    const int t  = threadIdx.x;
    const int CH = (NN + 1023) / 1024;              // 98
    int lo = t * CH;
    int hi = lo + CH; if (hi > NN) hi = NN;
    int s = 0;
    for (int i = lo; i < hi; ++i) s += g_deg[i];
    part[t] = s;
    __syncthreads();
    // Hillis-Steele inclusive scan
    for (int off = 1; off < 1024; off <<= 1) {
        int v = (t >= off) ? part[t - off] : 0;
        __syncthreads();
        part[t] += v;
        __syncthreads();
    }
    int run = (t == 0) ? 0 : part[t - 1];
    for (int i = lo; i < hi; ++i) {
        g_start[i]  = run;
        g_cursor[i] = run;
        run += g_deg[i];
    }
}

__global__ void fill_kernel(const int* __restrict__ ei) {
    int e = blockIdx.x * blockDim.x + threadIdx.x;
    if (e >= EE) return;
    int s = ei[e];
    int d = ei[EE + e];
    int pos = atomicAdd(&g_cursor[d], 1);
    g_csr[pos] = s;
}

// ------------------------- fused GIN layer -----------------------------------
// hout = elu( relu( (hin + sum_nbr hin) @ Wa + ba ) @ Wb + bb )
// Block: 64 node rows, 256 threads (8 warps x 8 rows), 160KB dyn smem.
__global__ void __launch_bounds__(256, 1)
layer_kernel(const float* __restrict__ hin,
             const float* __restrict__ wa, const float* __restrict__ ba,
             const float* __restrict__ wb, const float* __restrict__ bb,
             float* __restrict__ hout) {
    extern __shared__ float smem[];
    float* sWA = smem;            // 16384 f
    float* sWB = smem + 16384;    // 16384 f
    float* sX  = smem + 32768;    // 64*128 = 8192 f

    const int tid  = threadIdx.x;
    const int lane = tid & 31;
    const int w    = tid >> 5;
    const int m0   = blockIdx.x * 64;

    // ---- weights into smem (coalesced float4) ----
    const float4* wa4  = reinterpret_cast<const float4*>(wa);
    const float4* wb4  = reinterpret_cast<const float4*>(wb);
    float4* sWA4 = reinterpret_cast<float4*>(sWA);
    float4* sWB4 = reinterpret_cast<float4*>(sWB);
#pragma unroll
    for (int it = 0; it < 16; ++it) {
        sWA4[tid + 256 * it] = wa4[tid + 256 * it];
        sWB4[tid + 256 * it] = wb4[tid + 256 * it];
    }

    // ---- fused gather: sX[row] = hin[row] + sum_{src in N(row)} hin[src] ----
    const float4* hin4 = reinterpret_cast<const float4*>(hin);
    float4* sX4 = reinterpret_cast<float4*>(sX);
#pragma unroll
    for (int i = 0; i < 8; ++i) {
        int row = m0 + w * 8 + i;
        float4 acc = make_float4(0.f, 0.f, 0.f, 0.f);
        if (row < NN) {
            acc = __ldg(&hin4[(size_t)row * 32 + lane]);
            int st = g_start[row];
            int dg = g_deg[row];
            for (int j0 = 0; j0 < dg; j0 += 32) {
                int cnt = dg - j0; if (cnt > 32) cnt = 32;
                int nb = 0;
                if (lane < cnt) nb = g_csr[st + j0 + lane];
                int k = 0;
                for (; k + 4 <= cnt; k += 4) {
                    int s0 = __shfl_sync(0xFFFFFFFFu, nb, k);
                    int s1 = __shfl_sync(0xFFFFFFFFu, nb, k + 1);
                    int s2 = __shfl_sync(0xFFFFFFFFu, nb, k + 2);
                    int s3 = __shfl_sync(0xFFFFFFFFu, nb, k + 3);
                    float4 v0 = __ldg(&hin4[(size_t)s0 * 32 + lane]);
                    float4 v1 = __ldg(&hin4[(size_t)s1 * 32 + lane]);
                    float4 v2 = __ldg(&hin4[(size_t)s2 * 32 + lane]);
                    float4 v3 = __ldg(&hin4[(size_t)s3 * 32 + lane]);
                    acc.x += v0.x + v1.x + v2.x + v3.x;
                    acc.y += v0.y + v1.y + v2.y + v3.y;
                    acc.z += v0.z + v1.z + v2.z + v3.z;
                    acc.w += v0.w + v1.w + v2.w + v3.w;
                }
                for (; k < cnt; ++k) {
                    int s0 = __shfl_sync(0xFFFFFFFFu, nb, k);
                    float4 v = __ldg(&hin4[(size_t)s0 * 32 + lane]);
                    acc.x += v.x; acc.y += v.y; acc.z += v.z; acc.w += v.w;
                }
            }
        }
        sX4[(size_t)(w * 8 + i) * 32 + lane] = acc;
    }
    __syncthreads();

    const int ct = lane;   // col group: cols [ct*4, ct*4+4)
    const int rt = w;      // row group: rows [rt*8, rt*8+8)

    // ---- GEMM 1: sX @ Wa + ba -> ReLU -> sX ----
    unsigned long long acc01[8], acc23[8];
    {
        float4 bA = reinterpret_cast<const float4*>(ba)[ct];
#pragma unroll
        for (int i = 0; i < 8; ++i) {
            acc01[i] = pack2(bA.x, bA.y);
            acc23[i] = pack2(bA.z, bA.w);
        }
    }
#pragma unroll 4
    for (int k = 0; k < HIDD; ++k) {
        float4 bcol = reinterpret_cast<const float4*>(sWA + k * HIDD)[ct];
        unsigned long long b01 = pack2(bcol.x, bcol.y);
        unsigned long long b23 = pack2(bcol.z, bcol.w);
#pragma unroll
        for (int i = 0; i < 8; ++i) {
            float a = sX[(rt * 8 + i) * HIDD + k];   // warp broadcast
            unsigned long long aa = pack2(a, a);
            acc01[i] = fma2(aa, b01, acc01[i]);
            acc23[i] = fma2(aa, b23, acc23[i]);
        }
    }
    __syncthreads();
#pragma unroll
    for (int i = 0; i < 8; ++i) {
        float2 p = unpack2(acc01[i]);
        float2 q = unpack2(acc23[i]);
        float4 v = make_float4(fmaxf(p.x, 0.f), fmaxf(p.y, 0.f),
                               fmaxf(q.x, 0.f), fmaxf(q.y, 0.f));
        reinterpret_cast<float4*>(sX + (rt * 8 + i) * HIDD)[ct] = v;
    }
    __syncthreads();

    // ---- GEMM 2: sX @ Wb + bb -> ELU -> hout ----
    {
        float4 bB = reinterpret_cast<const float4*>(bb)[ct];
#pragma unroll
        for (int i = 0; i < 8; ++i) {
            acc01[i] = pack2(bB.x, bB.y);
            acc23[i] = pack2(bB.z, bB.w);
        }
    }
#pragma unroll 4
    for (int k = 0; k < HIDD; ++k) {
        float4 bcol = reinterpret_cast<const float4*>(sWB + k * HIDD)[ct];
        unsigned long long b01 = pack2(bcol.x, bcol.y);
        unsigned long long b23 = pack2(bcol.z, bcol.w);
#pragma unroll
        for (int i = 0; i < 8; ++i) {
            float a = sX[(rt * 8 + i) * HIDD + k];
            unsigned long long aa = pack2(a, a);
            acc01[i] = fma2(aa, b01, acc01[i]);
            acc23[i] = fma2(aa, b23, acc23[i]);
        }
    }
#pragma unroll
    for (int i = 0; i < 8; ++i) {
        int row = m0 + rt * 8 + i;
        if (row < NN) {
            float2 p = unpack2(acc01[i]);
            float2 q = unpack2(acc23[i]);
            float4 v;
            v.x = p.x > 0.f ? p.x : expf(p.x) - 1.f;
            v.y = p.y > 0.f ? p.y : expf(p.y) - 1.f;
            v.z = q.x > 0.f ? q.x : expf(q.x) - 1.f;
            v.w = q.y > 0.f ? q.y : expf(q.y) - 1.f;
            reinterpret_cast<float4*>(hout + (size_t)row * HIDD)[ct] = v;
        }
    }
}

// ------------------------- final head ---------------------------------------
__global__ void final_kernel(const float* __restrict__ h,
                             const float* __restrict__ lw,
                             const float* __restrict__ lb,
                             float* __restrict__ out) {
    int warp = (blockIdx.x * blockDim.x + threadIdx.x) >> 5;
    int lane = threadIdx.x & 31;
    if (warp >= NN) return;
    const float* row = h + (size_t)warp * HIDD;
    float s = 0.f;
#pragma unroll
    for (int i = 0; i < 4; ++i)
        s += row[lane + 32 * i] * lw[lane + 32 * i];
#pragma unroll
    for (int o = 16; o; o >>= 1)
        s += __shfl_xor_sync(0xFFFFFFFFu, s, o);
    if (lane == 0)
        out[warp] = 1.f / (1.f + expf(-(s + lb[0])));
}

// -----------------------------------------------------------------------------
extern "C" void kernel_launch(void* const* d_in, const int* in_sizes, int n_in,
                              void* d_out, int out_size) {
    const float* x  = (const float*)d_in[0];
    const int*   ei = (const int*)d_in[1];   // int32 (jax x64 disabled)
    const float* Wa[3] = { (const float*)d_in[2],  (const float*)d_in[6],  (const float*)d_in[10] };
    const float* Ba[3] = { (const float*)d_in[3],  (const float*)d_in[7],  (const float*)d_in[11] };
    const float* Wb[3] = { (const float*)d_in[4],  (const float*)d_in[8],  (const float*)d_in[12] };
    const float* Bb[3] = { (const float*)d_in[5],  (const float*)d_in[9],  (const float*)d_in[13] };
    const float* lin_w = (const float*)d_in[14];
    const float* lin_b = (const float*)d_in[15];
    float* out = (float*)d_out;

    float *h0, *h1;
    cudaGetSymbolAddress((void**)&h0, g_h0);
    cudaGetSymbolAddress((void**)&h1, g_h1);

    cudaFuncSetAttribute(layer_kernel,
                         cudaFuncAttributeMaxDynamicSharedMemorySize, 163840);

    // ---- CSR build (once per launch, reused by all 3 layers) ----
    zero_deg_kernel<<<(NN + 255) / 256, 256>>>();
    deg_kernel     <<<(EE + 255) / 256, 256>>>(ei);
    scan_kernel    <<<1, 1024>>>();
    fill_kernel    <<<(EE + 255) / 256, 256>>>(ei);

    // ---- 3 fused GIN layers ----
    const int mblocks = (NN + 63) / 64;
    const float* hin = x;
    float* bufs[3] = { h0, h1, h0 };
    for (int l = 0; l < 3; ++l) {
        layer_kernel<<<mblocks, 256, 163840>>>(hin, Wa[l], Ba[l], Wb[l], Bb[l], bufs[l]);
        hin = bufs[l];
    }

    final_kernel<<<(NN * 32 + 255) / 256, 256>>>(hin, lin_w, lin_b, out);
}

// round 4
// speedup vs baseline: 1.4156x; 1.4156x over previous
#include <cuda_runtime.h>
#include <math.h>

#define NN   100000
#define EE   1600000
#define HIDD 128

// ------------------------- scratch (__device__ globals) ---------------------
__device__ int   g_deg   [NN];
__device__ int   g_start [NN];
__device__ int   g_cursor[NN];
__device__ int   g_csr   [EE];               // src node per (dst-grouped) slot
__device__ float g_xsum[(size_t)NN * HIDD];  // h[v] + sum of neighbor rows
__device__ float g_h0  [(size_t)NN * HIDD];
__device__ float g_h1  [(size_t)NN * HIDD];

// ------------------------- f32x2 packed helpers -----------------------------
__device__ __forceinline__ unsigned long long pack2(float lo, float hi) {
    unsigned long long r;
    asm("mov.b64 %0, {%1, %2};" : "=l"(r) : "f"(lo), "f"(hi));
    return r;
}
__device__ __forceinline__ unsigned long long fma2(unsigned long long a,
                                                   unsigned long long b,
                                                   unsigned long long c) {
    unsigned long long d;
    asm("fma.rn.f32x2 %0, %1, %2, %3;" : "=l"(d) : "l"(a), "l"(b), "l"(c));
    return d;
}
__device__ __forceinline__ float2 unpack2(unsigned long long v) {
    float2 f;
    asm("mov.b64 {%0, %1}, %2;" : "=f"(f.x), "=f"(f.y) : "l"(v));
    return f;
}

// ------------------------- CSR build ----------------------------------------
__global__ void deg_kernel(const int* __restrict__ ei) {
    int e = blockIdx.x * blockDim.x + threadIdx.x;
    if (e < EE) atomicAdd(&g_deg[ei[EE + e]], 1);
}

// single-block exclusive scan over 100k degrees -> start & cursor
__global__ void scan_kernel() {
    __shared__ int part[1024];
    const int t  = threadIdx.x;
    const int CH = (NN + 1023) / 1024;              // 98
    int lo = t * CH;
    int hi = lo + CH; if (hi > NN) hi = NN;
    int s = 0;
    for (int i = lo; i < hi; ++i) s += g_deg[i];
    part[t] = s;
    __syncthreads();
    for (int off = 1; off < 1024; off <<= 1) {
        int v = (t >= off) ? part[t - off] : 0;
        __syncthreads();
        part[t] += v;
        __syncthreads();
    }
    int run = (t == 0) ? 0 : part[t - 1];
    for (int i = lo; i < hi; ++i) {
        g_start[i]  = run;
        g_cursor[i] = run;
        run += g_deg[i];
    }
}

__global__ void fill_kernel(const int* __restrict__ ei) {
    int e = blockIdx.x * blockDim.x + threadIdx.x;
    if (e >= EE) return;
    int s = ei[e];
    int d = ei[EE + e];
    int pos = atomicAdd(&g_cursor[d], 1);
    g_csr[pos] = s;
}

// ------------------------- gather: xsum[v] = h[v] + sum_{u in N(v)} h[u] ----
// One warp per node. Lane owns a float4 (16B) of the 512B row -> each neighbor
// row read is one fully-coalesced LDG.128 per lane. Unroll 4 for MLP.
__global__ void __launch_bounds__(256)
gather_kernel(const float* __restrict__ hin, float* __restrict__ xsum) {
    int w    = (blockIdx.x * blockDim.x + threadIdx.x) >> 5;
    int lane = threadIdx.x & 31;
    if (w >= NN) return;

    const float4* h4 = reinterpret_cast<const float4*>(hin);
    float4 acc = __ldg(&h4[(size_t)w * 32 + lane]);

    const int st = g_start[w];
    const int dg = g_deg[w];
    const int* __restrict__ csr = g_csr + st;

    int j = 0;
    for (; j + 4 <= dg; j += 4) {
        int n0 = __ldg(&csr[j]);
        int n1 = __ldg(&csr[j + 1]);
        int n2 = __ldg(&csr[j + 2]);
        int n3 = __ldg(&csr[j + 3]);
        float4 v0 = __ldg(&h4[(size_t)n0 * 32 + lane]);
        float4 v1 = __ldg(&h4[(size_t)n1 * 32 + lane]);
        float4 v2 = __ldg(&h4[(size_t)n2 * 32 + lane]);
        float4 v3 = __ldg(&h4[(size_t)n3 * 32 + lane]);
        acc.x += (v0.x + v1.x) + (v2.x + v3.x);
        acc.y += (v0.y + v1.y) + (v2.y + v3.y);
        acc.z += (v0.z + v1.z) + (v2.z + v3.z);
        acc.w += (v0.w + v1.w) + (v2.w + v3.w);
    }
    for (; j < dg; ++j) {
        int n0 = __ldg(&csr[j]);
        float4 v = __ldg(&h4[(size_t)n0 * 32 + lane]);
        acc.x += v.x; acc.y += v.y; acc.z += v.z; acc.w += v.w;
    }
    reinterpret_cast<float4*>(xsum)[(size_t)w * 32 + lane] = acc;
}

// ------------------------- MLP: hout = elu(relu(xsum@Wa+ba)@Wb+bb) ----------
// Block: 64 node rows, 256 threads (8 warps x 8 rows), 160KB dyn smem.
__global__ void __launch_bounds__(256, 1)
mlp_kernel(const float* __restrict__ xin,
           const float* __restrict__ wa, const float* __restrict__ ba,
           const float* __restrict__ wb, const float* __restrict__ bb,
           float* __restrict__ hout) {
    extern __shared__ float smem[];
    float* sWA = smem;            // 16384 f
    float* sWB = smem + 16384;    // 16384 f
    float* sX  = smem + 32768;    // 64*128 = 8192 f

    const int tid  = threadIdx.x;
    const int m0   = blockIdx.x * 64;

    // weights into smem (coalesced float4)
    const float4* wa4 = reinterpret_cast<const float4*>(wa);
    const float4* wb4 = reinterpret_cast<const float4*>(wb);
    float4* sWA4 = reinterpret_cast<float4*>(sWA);
    float4* sWB4 = reinterpret_cast<float4*>(sWB);
#pragma unroll
    for (int it = 0; it < 16; ++it) {
        sWA4[tid + 256 * it] = wa4[tid + 256 * it];
        sWB4[tid + 256 * it] = wb4[tid + 256 * it];
    }

    // X tile
    float4* sX4 = reinterpret_cast<float4*>(sX);
#pragma unroll
    for (int it = 0; it < 8; ++it) {
        int p   = tid + 256 * it;
        int row = p >> 5;
        float4 v = make_float4(0.f, 0.f, 0.f, 0.f);
        if (m0 + row < NN)
            v = __ldg(&reinterpret_cast<const float4*>(xin)[(size_t)(m0 + row) * 32 + (p & 31)]);
        sX4[p] = v;
    }
    __syncthreads();

    const int ct = tid & 31;
    const int rt = tid >> 5;

    // ---- GEMM 1 ----
    unsigned long long acc01[8], acc23[8];
    {
        float4 bA = reinterpret_cast<const float4*>(ba)[ct];
#pragma unroll
        for (int i = 0; i < 8; ++i) {
            acc01[i] = pack2(bA.x, bA.y);
            acc23[i] = pack2(bA.z, bA.w);
        }
    }
#pragma unroll 4
    for (int k = 0; k < HIDD; ++k) {
        float4 bcol = reinterpret_cast<const float4*>(sWA + k * HIDD)[ct];
        unsigned long long b01 = pack2(bcol.x, bcol.y);
        unsigned long long b23 = pack2(bcol.z, bcol.w);
#pragma unroll
        for (int i = 0; i < 8; ++i) {
            float a = sX[(rt * 8 + i) * HIDD + k];
            unsigned long long aa = pack2(a, a);
            acc01[i] = fma2(aa, b01, acc01[i]);
            acc23[i] = fma2(aa, b23, acc23[i]);
        }
    }
    __syncthreads();
#pragma unroll
    for (int i = 0; i < 8; ++i) {
        float2 p = unpack2(acc01[i]);
        float2 q = unpack2(acc23[i]);
        float4 v = make_float4(fmaxf(p.x, 0.f), fmaxf(p.y, 0.f),
                               fmaxf(q.x, 0.f), fmaxf(q.y, 0.f));
        reinterpret_cast<float4*>(sX + (rt * 8 + i) * HIDD)[ct] = v;
    }
    __syncthreads();

    // ---- GEMM 2 ----
    {
        float4 bB = reinterpret_cast<const float4*>(bb)[ct];
#pragma unroll
        for (int i = 0; i < 8; ++i) {
            acc01[i] = pack2(bB.x, bB.y);
            acc23[i] = pack2(bB.z, bB.w);
        }
    }
#pragma unroll 4
    for (int k = 0; k < HIDD; ++k) {
        float4 bcol = reinterpret_cast<const float4*>(sWB + k * HIDD)[ct];
        unsigned long long b01 = pack2(bcol.x, bcol.y);
        unsigned long long b23 = pack2(bcol.z, bcol.w);
#pragma unroll
        for (int i = 0; i < 8; ++i) {
            float a = sX[(rt * 8 + i) * HIDD + k];
            unsigned long long aa = pack2(a, a);
            acc01[i] = fma2(aa, b01, acc01[i]);
            acc23[i] = fma2(aa, b23, acc23[i]);
        }
    }
#pragma unroll
    for (int i = 0; i < 8; ++i) {
        int row = m0 + rt * 8 + i;
        if (row < NN) {
            float2 p = unpack2(acc01[i]);
            float2 q = unpack2(acc23[i]);
            float4 v;
            v.x = p.x > 0.f ? p.x : expf(p.x) - 1.f;
            v.y = p.y > 0.f ? p.y : expf(p.y) - 1.f;
            v.z = q.x > 0.f ? q.x : expf(q.x) - 1.f;
            v.w = q.y > 0.f ? q.y : expf(q.y) - 1.f;
            reinterpret_cast<float4*>(hout + (size_t)row * HIDD)[ct] = v;
        }
    }
}

// ------------------------- final head ---------------------------------------
__global__ void final_kernel(const float* __restrict__ h,
                             const float* __restrict__ lw,
                             const float* __restrict__ lb,
                             float* __restrict__ out) {
    int warp = (blockIdx.x * blockDim.x + threadIdx.x) >> 5;
    int lane = threadIdx.x & 31;
    if (warp >= NN) return;
    const float* row = h + (size_t)warp * HIDD;
    float s = 0.f;
#pragma unroll
    for (int i = 0; i < 4; ++i)
        s += row[lane + 32 * i] * lw[lane + 32 * i];
#pragma unroll
    for (int o = 16; o; o >>= 1)
        s += __shfl_xor_sync(0xFFFFFFFFu, s, o);
    if (lane == 0)
        out[warp] = 1.f / (1.f + expf(-(s + lb[0])));
}

// -----------------------------------------------------------------------------
extern "C" void kernel_launch(void* const* d_in, const int* in_sizes, int n_in,
                              void* d_out, int out_size) {
    const float* x  = (const float*)d_in[0];
    const int*   ei = (const int*)d_in[1];   // int32 (jax x64 disabled)
    const float* Wa[3] = { (const float*)d_in[2],  (const float*)d_in[6],  (const float*)d_in[10] };
    const float* Ba[3] = { (const float*)d_in[3],  (const float*)d_in[7],  (const float*)d_in[11] };
    const float* Wb[3] = { (const float*)d_in[4],  (const float*)d_in[8],  (const float*)d_in[12] };
    const float* Bb[3] = { (const float*)d_in[5],  (const float*)d_in[9],  (const float*)d_in[13] };
    const float* lin_w = (const float*)d_in[14];
    const float* lin_b = (const float*)d_in[15];
    float* out = (float*)d_out;

    float *xsum, *h0, *h1;
    int* degp;
    cudaGetSymbolAddress((void**)&xsum, g_xsum);
    cudaGetSymbolAddress((void**)&h0,   g_h0);
    cudaGetSymbolAddress((void**)&h1,   g_h1);
    cudaGetSymbolAddress((void**)&degp, g_deg);

    cudaFuncSetAttribute(mlp_kernel,
                         cudaFuncAttributeMaxDynamicSharedMemorySize, 163840);

    // ---- CSR build (once per launch, reused by all 3 layers) ----
    cudaMemsetAsync(degp, 0, NN * sizeof(int));
    deg_kernel <<<(EE + 255) / 256, 256>>>(ei);
    scan_kernel<<<1, 1024>>>();
    fill_kernel<<<(EE + 255) / 256, 256>>>(ei);

    // ---- 3 GIN layers: gather -> fused MLP ----
    const int gblocks = (NN * 32 + 255) / 256;   // one warp per node
    const int mblocks = (NN + 63) / 64;
    const float* hin = x;
    float* bufs[3] = { h0, h1, h0 };
    for (int l = 0; l < 3; ++l) {
        gather_kernel<<<gblocks, 256>>>(hin, xsum);
        mlp_kernel   <<<mblocks, 256, 163840>>>(xsum, Wa[l], Ba[l], Wb[l], Bb[l], bufs[l]);
        hin = bufs[l];
    }

    final_kernel<<<gblocks, 256>>>(hin, lin_w, lin_b, out);
}